// round 6
// baseline (speedup 1.0000x reference)
#include <cuda_runtime.h>
#include <math.h>

#define TPB 256
#define EPSF 1e-12f

__device__ __forceinline__ float sigmoidf_(float x) {
    return 1.0f / (1.0f + expf(-x));
}

// smooth_clamp with slope_l = 0 (all call sites use 0)
__device__ __forceinline__ float smooth_clamp(float x, float lb, float rb, float slope_r) {
    float t = (x - lb) / (rb - lb);
    float core = lb + (rb - lb) * sigmoidf_(4.0f * t - 2.0f);
    return core + slope_r * fmaxf(x - rb, 0.0f);
}

__global__ __launch_bounds__(TPB) void face_gs_kernel(
    const float* __restrict__ pa, const float* __restrict__ pb, const float* __restrict__ pc,
    const float* __restrict__ rotz,
    const float* __restrict__ gsx, const float* __restrict__ gsy, const float* __restrict__ gsz,
    const float* __restrict__ color, const float* __restrict__ logop,
    float* __restrict__ out, int F)
{
    __shared__ float s[TPB * 14];

    const int tid = threadIdx.x;
    const int blockBase = blockIdx.x * TPB;
    const int i = blockBase + tid;
    const int valid = min(TPB, F - blockBase);

    if (i < F) {
        // --- load vertices ---
        const float ax0 = pa[3*i+0], ay0 = pa[3*i+1], az0 = pa[3*i+2];
        const float bx0 = pb[3*i+0], by0 = pb[3*i+1], bz0 = pb[3*i+2];
        const float cx0 = pc[3*i+0], cy0 = pc[3*i+1], cz0 = pc[3*i+2];

        // --- face frame ---
        const float e1x = bx0 - ax0, e1y = by0 - ay0, e1z = bz0 - az0;
        const float e2x = cx0 - ax0, e2y = cy0 - ay0, e2z = cz0 - az0;

        // n = e1 x e2
        const float nx = e1y * e2z - e1z * e2y;
        const float ny = e1z * e2x - e1x * e2z;
        const float nz = e1x * e2y - e1y * e2x;

        const float n_norm = sqrtf(nx*nx + ny*ny + nz*nz);
        const float area   = 0.5f * n_norm;

        const float e1_norm = sqrtf(e1x*e1x + e1y*e1y + e1z*e1z);
        const float inv_e1  = 1.0f / (e1_norm + EPSF);
        const float inv_n   = 1.0f / (n_norm + EPSF);

        // columns of R: ax, ay, az
        const float axx = e1x * inv_e1, axy = e1y * inv_e1, axz = e1z * inv_e1;
        const float azx = nx  * inv_n,  azy = ny  * inv_n,  azz = nz  * inv_n;
        // ay = az x ax
        const float ayx = azy * axz - azz * axy;
        const float ayy = azz * axx - azx * axz;
        const float ayz = azx * axy - azy * axx;

        // centroid
        const float tx = (ax0 + bx0 + cx0) * (1.0f/3.0f);
        const float ty = (ay0 + by0 + cy0) * (1.0f/3.0f);
        const float tz = (az0 + bz0 + cz0) * (1.0f/3.0f);

        // --- rotation matrix -> quaternion (WXYZ), 4-case robust ---
        // R[r][c]: col0=ax, col1=ay, col2=az
        const float m00 = axx, m01 = ayx, m02 = azx;
        const float m10 = axy, m11 = ayy, m12 = azy;
        const float m20 = axz, m21 = ayz, m22 = azz;

        const float tr = m00 + m11 + m22;

        // argmax over [tr, m00, m11, m22], first-index tie-break (strict >)
        int idx = 0;
        float best = tr;
        if (m00 > best) { best = m00; idx = 1; }
        if (m11 > best) { best = m11; idx = 2; }
        if (m22 > best) { best = m22; idx = 3; }

        float qw, qx, qy, qz;
        if (idx == 0) {
            const float t0 = fmaxf(1.0f + tr, 1e-8f);
            const float s0 = 0.5f / sqrtf(t0);
            qw = t0 * s0;
            qx = (m21 - m12) * s0;
            qy = (m02 - m20) * s0;
            qz = (m10 - m01) * s0;
        } else if (idx == 1) {
            const float t1 = fmaxf(1.0f + m00 - m11 - m22, 1e-8f);
            const float s1 = 0.5f / sqrtf(t1);
            qw = (m21 - m12) * s1;
            qx = t1 * s1;
            qy = (m01 + m10) * s1;
            qz = (m02 + m20) * s1;
        } else if (idx == 2) {
            const float t2 = fmaxf(1.0f - m00 + m11 - m22, 1e-8f);
            const float s2 = 0.5f / sqrtf(t2);
            qw = (m02 - m20) * s2;
            qx = (m01 + m10) * s2;
            qy = t2 * s2;
            qz = (m12 + m21) * s2;
        } else {
            const float t3 = fmaxf(1.0f - m00 - m11 + m22, 1e-8f);
            const float s3 = 0.5f / sqrtf(t3);
            qw = (m10 - m01) * s3;
            qx = (m02 + m20) * s3;
            qy = (m12 + m21) * s3;
            qz = t3 * s3;
        }

        // --- multiply by local z-rotation quaternion (ch, 0, 0, sh) ---
        const float half = rotz[i] * 0.5f;
        float sh, ch;
        sincosf(half, &sh, &ch);
        const float ww = qw * ch - qz * sh;
        const float wx = qx * ch + qy * sh;
        const float wy = qy * ch - qx * sh;
        const float wz = qw * sh + qz * ch;

        // --- scales ---
        const float sf = sqrtf(area);
        const float sx = sf * smooth_clamp(expf(gsx[i]), 0.1f,   3.0f,  0.005f);
        const float sy = sf * smooth_clamp(expf(gsy[i]), 0.1f,   3.0f,  0.005f);
        const float sz = smooth_clamp(sf * expf(gsz[i]), 0.001f, 0.01f, 0.005f);

        const float opac = expf(logop[i]);

        const float col_r = color[3*i+0];
        const float col_g = color[3*i+1];
        const float col_b = color[3*i+2];

        // --- stage into shared memory: mean(3)|quat(4)|scale(3)|color(3)|opacity(1) ---
        float* row = s + tid * 14;
        row[0]  = tx;   row[1]  = ty;   row[2]  = tz;
        row[3]  = ww;   row[4]  = wx;   row[5]  = wy;   row[6] = wz;
        row[7]  = sx;   row[8]  = sy;   row[9]  = sz;
        row[10] = col_r; row[11] = col_g; row[12] = col_b;
        row[13] = opac;
    }
    __syncthreads();

    // --- cooperative coalesced float4 flush of the block's contiguous output slab ---
    const int n_floats = valid * 14;
    float* gbase = out + (size_t)blockBase * 14;
    const int n4 = n_floats >> 2;
    const float4* s4 = reinterpret_cast<const float4*>(s);
    float4* g4 = reinterpret_cast<float4*>(gbase);
    for (int k = tid; k < n4; k += TPB) {
        g4[k] = s4[k];
    }
    // scalar tail (only possible for a ragged last block)
    for (int k = (n4 << 2) + tid; k < n_floats; k += TPB) {
        gbase[k] = s[k];
    }
}

extern "C" void kernel_launch(void* const* d_in, const int* in_sizes, int n_in,
                              void* d_out, int out_size) {
    const float* pa    = (const float*)d_in[0];
    const float* pb    = (const float*)d_in[1];
    const float* pc    = (const float*)d_in[2];
    const float* rotz  = (const float*)d_in[3];
    const float* gsx   = (const float*)d_in[4];
    const float* gsy   = (const float*)d_in[5];
    const float* gsz   = (const float*)d_in[6];
    const float* color = (const float*)d_in[7];
    const float* logop = (const float*)d_in[8];
    float* out = (float*)d_out;

    const int F = in_sizes[3];  // gp_rot_z element count == number of faces
    const int blocks = (F + TPB - 1) / TPB;
    face_gs_kernel<<<blocks, TPB>>>(pa, pb, pc, rotz, gsx, gsy, gsz, color, logop, out, F);
}

// round 13
// speedup vs baseline: 1.2932x; 1.2932x over previous
#include <cuda_runtime.h>
#include <math.h>

#define TPB 256
#define EPSF 1e-12f

// fast sigmoid: MUFU ex2-based exp + approximate reciprocal (~2^-21 rel err)
__device__ __forceinline__ float fast_sigmoid(float x) {
    return __fdividef(1.0f, 1.0f + __expf(-x));
}

// smooth_clamp with slope_l = 0 (all call sites use 0)
__device__ __forceinline__ float smooth_clamp(float x, float lb, float rb, float slope_r) {
    float t = (x - lb) * __fdividef(1.0f, rb - lb);
    float core = lb + (rb - lb) * fast_sigmoid(4.0f * t - 2.0f);
    return core + slope_r * fmaxf(x - rb, 0.0f);
}

__global__ __launch_bounds__(TPB) void face_gs_kernel(
    const float* __restrict__ pa, const float* __restrict__ pb, const float* __restrict__ pc,
    const float* __restrict__ rotz,
    const float* __restrict__ gsx, const float* __restrict__ gsy, const float* __restrict__ gsz,
    const float* __restrict__ color, const float* __restrict__ logop,
    float* __restrict__ out, int F)
{
    __shared__ float s[TPB * 14];

    const int tid = threadIdx.x;
    const int blockBase = blockIdx.x * TPB;
    const int i = blockBase + tid;
    const int valid = min(TPB, F - blockBase);

    if (i < F) {
        // --- load vertices ---
        const float ax0 = pa[3*i+0], ay0 = pa[3*i+1], az0 = pa[3*i+2];
        const float bx0 = pb[3*i+0], by0 = pb[3*i+1], bz0 = pb[3*i+2];
        const float cx0 = pc[3*i+0], cy0 = pc[3*i+1], cz0 = pc[3*i+2];
        const float rz_in = rotz[i];
        const float vx_in = gsx[i], vy_in = gsy[i], vz_in = gsz[i];
        const float lop   = logop[i];
        const float col_r = color[3*i+0];
        const float col_g = color[3*i+1];
        const float col_b = color[3*i+2];

        // --- face frame ---
        const float e1x = bx0 - ax0, e1y = by0 - ay0, e1z = bz0 - az0;
        const float e2x = cx0 - ax0, e2y = cy0 - ay0, e2z = cz0 - az0;

        // n = e1 x e2
        const float nx = e1y * e2z - e1z * e2y;
        const float ny = e1z * e2x - e1x * e2z;
        const float nz = e1x * e2y - e1y * e2x;

        const float nn  = nx*nx + ny*ny + nz*nz;
        const float ee  = e1x*e1x + e1y*e1y + e1z*e1z;

        const float n_norm  = __fsqrt_rn(nn);       // exact sqrt (cheap MUFU+Newton)
        const float e1_norm = __fsqrt_rn(ee);
        const float area    = 0.5f * n_norm;

        const float inv_e1 = __fdividef(1.0f, e1_norm + EPSF);
        const float inv_n  = __fdividef(1.0f, n_norm + EPSF);

        // columns of R: ax, ay, az
        const float axx = e1x * inv_e1, axy = e1y * inv_e1, axz = e1z * inv_e1;
        const float azx = nx  * inv_n,  azy = ny  * inv_n,  azz = nz  * inv_n;
        // ay = az x ax
        const float ayx = azy * axz - azz * axy;
        const float ayy = azz * axx - azx * axz;
        const float ayz = azx * axy - azy * axx;

        // centroid
        const float tx = (ax0 + bx0 + cx0) * (1.0f/3.0f);
        const float ty = (ay0 + by0 + cy0) * (1.0f/3.0f);
        const float tz = (az0 + bz0 + cz0) * (1.0f/3.0f);

        // --- rotation matrix -> quaternion (WXYZ), 4-case robust ---
        // R[r][c]: col0=ax, col1=ay, col2=az
        const float m00 = axx, m01 = ayx, m02 = azx;
        const float m10 = axy, m11 = ayy, m12 = azy;
        const float m20 = axz, m21 = ayz, m22 = azz;

        const float tr = m00 + m11 + m22;

        // argmax over [tr, m00, m11, m22], first-index tie-break (strict >)
        int idx = 0;
        float best = tr;
        if (m00 > best) { best = m00; idx = 1; }
        if (m11 > best) { best = m11; idx = 2; }
        if (m22 > best) { best = m22; idx = 3; }

        float qw, qx, qy, qz;
        if (idx == 0) {
            const float t0 = fmaxf(1.0f + tr, 1e-8f);
            const float s0 = 0.5f * rsqrtf(t0);
            qw = t0 * s0;
            qx = (m21 - m12) * s0;
            qy = (m02 - m20) * s0;
            qz = (m10 - m01) * s0;
        } else if (idx == 1) {
            const float t1 = fmaxf(1.0f + m00 - m11 - m22, 1e-8f);
            const float s1 = 0.5f * rsqrtf(t1);
            qw = (m21 - m12) * s1;
            qx = t1 * s1;
            qy = (m01 + m10) * s1;
            qz = (m02 + m20) * s1;
        } else if (idx == 2) {
            const float t2 = fmaxf(1.0f - m00 + m11 - m22, 1e-8f);
            const float s2 = 0.5f * rsqrtf(t2);
            qw = (m02 - m20) * s2;
            qx = (m01 + m10) * s2;
            qy = t2 * s2;
            qz = (m12 + m21) * s2;
        } else {
            const float t3 = fmaxf(1.0f - m00 - m11 + m22, 1e-8f);
            const float s3 = 0.5f * rsqrtf(t3);
            qw = (m10 - m01) * s3;
            qx = (m02 + m20) * s3;
            qy = (m12 + m21) * s3;
            qz = t3 * s3;
        }

        // --- multiply by local z-rotation quaternion (ch, 0, 0, sh) ---
        // |half| ~ N(0, 0.5): tiny range, MUFU sin/cos plenty accurate
        const float half = rz_in * 0.5f;
        const float sh = __sinf(half);
        const float ch = __cosf(half);
        const float ww = qw * ch - qz * sh;
        const float wx = qx * ch + qy * sh;
        const float wy = qy * ch - qx * sh;
        const float wz = qw * sh + qz * ch;

        // --- scales ---
        const float sf = __fsqrt_rn(area);
        const float sx = sf * smooth_clamp(__expf(vx_in), 0.1f,   3.0f,  0.005f);
        const float sy = sf * smooth_clamp(__expf(vy_in), 0.1f,   3.0f,  0.005f);
        const float sz = smooth_clamp(sf * __expf(vz_in), 0.001f, 0.01f, 0.005f);

        const float opac = __expf(lop);

        // --- stage into shared memory: mean(3)|quat(4)|scale(3)|color(3)|opacity(1) ---
        float* row = s + tid * 14;
        row[0]  = tx;   row[1]  = ty;   row[2]  = tz;
        row[3]  = ww;   row[4]  = wx;   row[5]  = wy;   row[6] = wz;
        row[7]  = sx;   row[8]  = sy;   row[9]  = sz;
        row[10] = col_r; row[11] = col_g; row[12] = col_b;
        row[13] = opac;
    }
    __syncthreads();

    // --- cooperative coalesced float4 flush of the block's contiguous output slab ---
    const int n_floats = valid * 14;
    float* gbase = out + (size_t)blockBase * 14;
    const int n4 = n_floats >> 2;
    const float4* s4 = reinterpret_cast<const float4*>(s);
    float4* g4 = reinterpret_cast<float4*>(gbase);
    for (int k = tid; k < n4; k += TPB) {
        g4[k] = s4[k];
    }
    // scalar tail (only possible for a ragged last block)
    for (int k = (n4 << 2) + tid; k < n_floats; k += TPB) {
        gbase[k] = s[k];
    }
}

extern "C" void kernel_launch(void* const* d_in, const int* in_sizes, int n_in,
                              void* d_out, int out_size) {
    const float* pa    = (const float*)d_in[0];
    const float* pb    = (const float*)d_in[1];
    const float* pc    = (const float*)d_in[2];
    const float* rotz  = (const float*)d_in[3];
    const float* gsx   = (const float*)d_in[4];
    const float* gsy   = (const float*)d_in[5];
    const float* gsz   = (const float*)d_in[6];
    const float* color = (const float*)d_in[7];
    const float* logop = (const float*)d_in[8];
    float* out = (float*)d_out;

    const int F = in_sizes[3];  // gp_rot_z element count == number of faces
    const int blocks = (F + TPB - 1) / TPB;
    face_gs_kernel<<<blocks, TPB>>>(pa, pb, pc, rotz, gsx, gsy, gsz, color, logop, out, F);
}

// round 17
// speedup vs baseline: 1.3012x; 1.0062x over previous
#include <cuda_runtime.h>
#include <math.h>

#define TPB 256

// smooth_clamp with slope_l = 0, constants pre-folded:
//   y = 4*(x-lb)/(rb-lb) - 2 = x*c1 + c0,  c1 = 4/(rb-lb), c0 = -(4*lb/(rb-lb) + 2)
//   core = lb + (rb-lb)*sigmoid(y);  + slope_r * max(x-rb, 0)
__device__ __forceinline__ float smooth_clamp_f(float x, float c1, float c0,
                                                float lb, float w, float rb, float sr) {
    const float y    = fmaf(x, c1, c0);
    const float sig  = __fdividef(1.0f, 1.0f + __expf(-y));
    const float core = fmaf(w, sig, lb);
    return fmaf(sr, fmaxf(x - rb, 0.0f), core);
}

__global__ __launch_bounds__(TPB) void face_gs_kernel(
    const float* __restrict__ pa, const float* __restrict__ pb, const float* __restrict__ pc,
    const float* __restrict__ rotz,
    const float* __restrict__ gsx, const float* __restrict__ gsy, const float* __restrict__ gsz,
    const float* __restrict__ color, const float* __restrict__ logop,
    float* __restrict__ out, int F)
{
    __shared__ float s[TPB * 14];

    const int tid = threadIdx.x;
    const int blockBase = blockIdx.x * TPB;
    const int i = blockBase + tid;
    const int valid = min(TPB, F - blockBase);

    if (i < F) {
        // --- loads ---
        const float ax0 = pa[3*i+0], ay0 = pa[3*i+1], az0 = pa[3*i+2];
        const float bx0 = pb[3*i+0], by0 = pb[3*i+1], bz0 = pb[3*i+2];
        const float cx0 = pc[3*i+0], cy0 = pc[3*i+1], cz0 = pc[3*i+2];
        const float rz_in = rotz[i];
        const float vx_in = gsx[i], vy_in = gsy[i], vz_in = gsz[i];
        const float lop   = logop[i];
        const float col_r = color[3*i+0];
        const float col_g = color[3*i+1];
        const float col_b = color[3*i+2];

        // --- face frame ---
        const float e1x = bx0 - ax0, e1y = by0 - ay0, e1z = bz0 - az0;
        const float e2x = cx0 - ax0, e2y = cy0 - ay0, e2z = cz0 - az0;

        const float nx = e1y * e2z - e1z * e2y;
        const float ny = e1z * e2x - e1x * e2z;
        const float nz = e1x * e2y - e1y * e2x;

        const float nn = nx*nx + ny*ny + nz*nz;
        const float ee = e1x*e1x + e1y*e1y + e1z*e1z;

        const float n_norm = __fsqrt_rn(nn);
        const float area   = 0.5f * n_norm;

        // direct rsqrt normalization (eps shift ~1e-12 relative, negligible)
        const float inv_e1 = rsqrtf(ee);
        const float inv_n  = rsqrtf(nn);

        const float axx = e1x * inv_e1, axy = e1y * inv_e1, axz = e1z * inv_e1;
        const float azx = nx  * inv_n,  azy = ny  * inv_n,  azz = nz  * inv_n;
        const float ayx = azy * axz - azz * axy;
        const float ayy = azz * axx - azx * axz;
        const float ayz = azx * axy - azy * axx;

        const float tx = (ax0 + bx0 + cx0) * (1.0f/3.0f);
        const float ty = (ay0 + by0 + cy0) * (1.0f/3.0f);
        const float tz = (az0 + bz0 + cz0) * (1.0f/3.0f);

        // --- rotation matrix -> quaternion, branchless 4-case ---
        const float m00 = axx, m01 = ayx, m02 = azx;
        const float m10 = axy, m11 = ayy, m12 = azy;
        const float m20 = axz, m21 = ayz, m22 = azz;

        const float tr = m00 + m11 + m22;

        // shared subexpressions
        const float d0 = m21 - m12, d1 = m02 - m20, d2 = m10 - m01;
        const float a0 = m01 + m10, a1 = m02 + m20, a2 = m12 + m21;

        // sequential argmax (first-max-wins) as predicates
        const float best1 = fmaxf(tr, m00);
        const bool  c1b   = m00 > tr;
        const bool  c2b   = m11 > best1;
        const float best2 = fmaxf(m11, best1);
        const bool  c3b   = m22 > best2;

        const float t0 = fmaxf(1.0f + tr,               1e-8f);
        const float t1 = fmaxf(1.0f + m00 - m11 - m22,  1e-8f);
        const float t2 = fmaxf(1.0f - m00 + m11 - m22,  1e-8f);
        const float t3 = fmaxf(1.0f - m00 - m11 + m22,  1e-8f);

        const float tsel = c3b ? t3 : (c2b ? t2 : (c1b ? t1 : t0));
        const float sq   = 0.5f * rsqrtf(tsel);

        // per-case component tables: (case0, case1, case2, case3)
        // qw: t0, d0, d1, d2 | qx: d0, t1, a0, a1 | qy: d1, a0, t2, a2 | qz: d2, a1, a2, t3
        const float qw = (c3b ? d2 : (c2b ? d1 : (c1b ? d0 : t0))) * sq;
        const float qx = (c3b ? a1 : (c2b ? a0 : (c1b ? t1 : d0))) * sq;
        const float qy = (c3b ? a2 : (c2b ? t2 : (c1b ? a0 : d1))) * sq;
        const float qz = (c3b ? t3 : (c2b ? a2 : (c1b ? a1 : d2))) * sq;

        // --- compose with local z-rotation (ch, 0, 0, sh) ---
        const float half = rz_in * 0.5f;
        const float sh = __sinf(half);
        const float ch = __cosf(half);
        const float ww = qw * ch - qz * sh;
        const float wx = qx * ch + qy * sh;
        const float wy = qy * ch - qx * sh;
        const float wz = qw * sh + qz * ch;

        // --- scales (constants folded: (0.1,3.0): c1=4/2.9, c0=-(0.4/2.9+2);
        //     (0.001,0.01): c1=4/0.009, c0=-(0.004/0.009+2)) ---
        const float sf = __fsqrt_rn(area);
        const float sx = sf * smooth_clamp_f(__expf(vx_in),
                            1.37931034f, -2.13793103f, 0.1f, 2.9f, 3.0f, 0.005f);
        const float sy = sf * smooth_clamp_f(__expf(vy_in),
                            1.37931034f, -2.13793103f, 0.1f, 2.9f, 3.0f, 0.005f);
        const float sz = smooth_clamp_f(sf * __expf(vz_in),
                            444.444444f, -2.44444444f, 0.001f, 0.009f, 0.01f, 0.005f);

        const float opac = __expf(lop);

        // --- stage row: mean(3)|quat(4)|scale(3)|color(3)|opacity(1) ---
        float* row = s + tid * 14;
        row[0]  = tx;   row[1]  = ty;   row[2]  = tz;
        row[3]  = ww;   row[4]  = wx;   row[5]  = wy;   row[6] = wz;
        row[7]  = sx;   row[8]  = sy;   row[9]  = sz;
        row[10] = col_r; row[11] = col_g; row[12] = col_b;
        row[13] = opac;
    }
    __syncthreads();

    // --- cooperative coalesced float4 flush ---
    const int n_floats = valid * 14;
    float* gbase = out + (size_t)blockBase * 14;
    const int n4 = n_floats >> 2;
    const float4* s4 = reinterpret_cast<const float4*>(s);
    float4* g4 = reinterpret_cast<float4*>(gbase);
    for (int k = tid; k < n4; k += TPB) {
        g4[k] = s4[k];
    }
    for (int k = (n4 << 2) + tid; k < n_floats; k += TPB) {
        gbase[k] = s[k];
    }
}

extern "C" void kernel_launch(void* const* d_in, const int* in_sizes, int n_in,
                              void* d_out, int out_size) {
    const float* pa    = (const float*)d_in[0];
    const float* pb    = (const float*)d_in[1];
    const float* pc    = (const float*)d_in[2];
    const float* rotz  = (const float*)d_in[3];
    const float* gsx   = (const float*)d_in[4];
    const float* gsy   = (const float*)d_in[5];
    const float* gsz   = (const float*)d_in[6];
    const float* color = (const float*)d_in[7];
    const float* logop = (const float*)d_in[8];
    float* out = (float*)d_out;

    const int F = in_sizes[3];
    const int blocks = (F + TPB - 1) / TPB;
    face_gs_kernel<<<blocks, TPB>>>(pa, pb, pc, rotz, gsx, gsy, gsz, color, logop, out, F);
}